// round 10
// baseline (speedup 1.0000x reference)
#include <cuda_runtime.h>
#include <cuda_fp16.h>
#include <math_constants.h>
#include <cstdint>

#define TOKENS  8192
#define HIDDEN  6144
#define EXPERTS 768
#define TOPK    12
#define NCAND   13
#define RSCALE  2.5f
#define TAU     1e-4f

// ---------------- GEMM config ----------------
#define BM 128
#define BN 128
#define BK 32
#define NST   (HIDDEN / BK)     // 192
#define NTILE ((TOKENS / BM) * (EXPERTS / BN))   // 384
#define GRID  296               // 2 CTAs per SM, persistent 2-tile split
#define NX    (EXPERTS / BN)    // 6
#define ROWB  80                // 64B data + 16B pad (LDSM conflict-free)
#define TILE_B  (128 * ROWB)    // 10240 per operand stage
#define STAGE_B (2 * TILE_B)
#define RING 3
#define GEMM_SMEM (RING * STAGE_B)   // 61440

__device__ __half g_Wh[(size_t)EXPERTS * HIDDEN];   // 9 MB
__device__ float  g_logits[(size_t)TOKENS * EXPERTS];

// ---------------- helpers ----------------
__device__ __forceinline__ uint32_t smem_u32(const void* p) {
    uint32_t a;
    asm("{ .reg .u64 t; cvta.to.shared.u64 t, %1; cvt.u32.u64 %0, t; }" : "=r"(a) : "l"(p));
    return a;
}
__device__ __forceinline__ uint2 f4_to_h4(float4 v) {
    __half2 p0 = __floats2half2_rn(v.x, v.y);
    __half2 p1 = __floats2half2_rn(v.z, v.w);
    return make_uint2(*(uint32_t*)&p0, *(uint32_t*)&p1);
}
__device__ __forceinline__ void cp16(uint32_t dst, const void* src) {
    asm volatile("cp.async.cg.shared.global [%0], [%1], 16;" :: "r"(dst), "l"(src) : "memory");
}
#define CP_COMMIT() asm volatile("cp.async.commit_group;" ::: "memory")
#define CP_WAIT1()  asm volatile("cp.async.wait_group 1;" ::: "memory")

__device__ __forceinline__ void ldm_x4(uint32_t* r, uint32_t addr) {
    asm volatile("ldmatrix.sync.aligned.m8n8.x4.shared.b16 {%0,%1,%2,%3}, [%4];"
                 : "=r"(r[0]), "=r"(r[1]), "=r"(r[2]), "=r"(r[3]) : "r"(addr));
}
__device__ __forceinline__ void mma16(float* c, const uint32_t* a, const uint32_t* b) {
    asm volatile(
        "mma.sync.aligned.m16n8k16.row.col.f32.f16.f16.f32 "
        "{%0,%1,%2,%3}, {%4,%5,%6,%7}, {%8,%9}, {%0,%1,%2,%3};"
        : "+f"(c[0]), "+f"(c[1]), "+f"(c[2]), "+f"(c[3])
        : "r"(a[0]), "r"(a[1]), "r"(a[2]), "r"(a[3]), "r"(b[0]), "r"(b[1]));
}

// ---------------------------------------------------------------------------
// fp32 -> fp16 conversion for W only (grid-stride over float4)
// ---------------------------------------------------------------------------
__global__ __launch_bounds__(256)
void cvt_kernel(const float4* __restrict__ in, uint2* __restrict__ out, int n4) {
    int i = blockIdx.x * blockDim.x + threadIdx.x;
    const int stride = gridDim.x * blockDim.x;
    for (; i < n4; i += stride) out[i] = f4_to_h4(in[i]);
}

// ---------------------------------------------------------------------------
// Persistent fused GEMM: A fp32 LDG->cvt->STS (1 stage ahead), B fp16 cp.async
// ring-3. 8 warps 2(m) x 4(n), warp tile 64x32. Each CTA: tiles bid, bid+296.
// ---------------------------------------------------------------------------
__global__ __launch_bounds__(256, 2)
void router_gemm_fused(const float* __restrict__ A) {
    extern __shared__ char smem[];
    const uint32_t smbase = smem_u32(smem);

    const int tid  = threadIdx.x;
    const int wid  = tid >> 5;
    const int lane = tid & 31;
    const int wm = wid & 1;
    const int wn = wid >> 1;

    // A writer map: 1024 fp32 16B-chunks; 4/thread. row = c>>3, cc = c&7.
    const int a_wrow = tid >> 3;         // +32*i
    const int a_wcc  = tid & 7;
    // B writer map: 512 fp16 16B-chunks; 2/thread. row = c>>2, cc = c&3.
    const int b_wrow = tid >> 2;         // +64*i
    const int b_wcc  = tid & 3;

    // frag address components
    const int a_row = wm * 64 + (lane & 7) + ((lane >> 3) & 1) * 8;  // + mi*16
    const int a_chl = (lane >> 4) & 1;                                // + w*2
    const int b_row = wn * 32 + (lane & 7) + ((lane >> 4) & 1) * 8;  // + p*16
    const int b_chl = (lane >> 3) & 1;                                // + w*2

    for (int t = blockIdx.x; t < NTILE; t += GRID) {
        const int m0 = (t / NX) * BM;
        const int n0 = (t % NX) * BN;
        const float*  Abase = A + (size_t)m0 * HIDDEN;
        const __half* Bbase = g_Wh + (size_t)n0 * HIDDEN;

        float acc[4][4][4];
        #pragma unroll
        for (int mi = 0; mi < 4; mi++)
            #pragma unroll
            for (int ni = 0; ni < 4; ni++)
                #pragma unroll
                for (int j = 0; j < 4; j++) acc[mi][ni][j] = 0.0f;

        float4 pa[4];

        auto ldgA = [&](int s) {
            const float* g = Abase + s * BK;
            #pragma unroll
            for (int i = 0; i < 4; i++)
                pa[i] = *(const float4*)(g + (size_t)(a_wrow + 32 * i) * HIDDEN + a_wcc * 4);
        };
        auto stsA = [&](int slot) {
            char* d = smem + slot * STAGE_B;
            #pragma unroll
            for (int i = 0; i < 4; i++)
                *(uint2*)(d + (a_wrow + 32 * i) * ROWB + a_wcc * 8) = f4_to_h4(pa[i]);
        };
        auto cpB = [&](int s, int slot) {
            const uint32_t d = smbase + slot * STAGE_B + TILE_B;
            const __half* g = Bbase + s * BK;
            #pragma unroll
            for (int i = 0; i < 2; i++)
                cp16(d + (b_wrow + 64 * i) * ROWB + b_wcc * 16,
                     g + (size_t)(b_wrow + 64 * i) * HIDDEN + b_wcc * 8);
        };

        // prologue
        ldgA(0); stsA(0);
        cpB(0, 0); CP_COMMIT();
        ldgA(1);
        cpB(1, 1); CP_COMMIT();

        for (int s = 0; s < NST; s++) {
            CP_WAIT1();
            if (s + 1 < NST) stsA((s + 1) % RING);   // regs hold stage s+1
            __syncthreads();
            if (s + 2 < NST) { ldgA(s + 2); cpB(s + 2, (s + 2) % RING); }
            CP_COMMIT();

            const uint32_t sA = smbase + (s % RING) * STAGE_B;
            const uint32_t sB = sA + TILE_B;

            #pragma unroll
            for (int w = 0; w < 2; w++) {          // two k16 windows of BK=32
                uint32_t af[4][4], bf[2][4];
                #pragma unroll
                for (int mi = 0; mi < 4; mi++)
                    ldm_x4(af[mi], sA + (uint32_t)((a_row + mi * 16) * ROWB + (w * 2 + a_chl) * 16));
                #pragma unroll
                for (int p = 0; p < 2; p++)
                    ldm_x4(bf[p], sB + (uint32_t)((b_row + p * 16) * ROWB + (w * 2 + b_chl) * 16));
                #pragma unroll
                for (int mi = 0; mi < 4; mi++) {
                    mma16(acc[mi][0], af[mi], &bf[0][0]);
                    mma16(acc[mi][1], af[mi], &bf[0][2]);
                    mma16(acc[mi][2], af[mi], &bf[1][0]);
                    mma16(acc[mi][3], af[mi], &bf[1][2]);
                }
            }
        }

        #pragma unroll
        for (int mi = 0; mi < 4; mi++) {
            const int row = m0 + wm * 64 + mi * 16 + (lane >> 2);
            #pragma unroll
            for (int ni = 0; ni < 4; ni++) {
                const int col = n0 + wn * 32 + ni * 8 + (lane & 3) * 2;
                *(float2*)(g_logits + (size_t)row * EXPERTS + col)       = make_float2(acc[mi][ni][0], acc[mi][ni][1]);
                *(float2*)(g_logits + (size_t)(row + 8) * EXPERTS + col) = make_float2(acc[mi][ni][2], acc[mi][ni][3]);
            }
        }
        __syncthreads();   // smem safe for next tile's prologue
    }
}

// ---------------------------------------------------------------------------
// Warp-per-token topk (unchanged from R9, passing at rel_err 2.8e-4).
// ---------------------------------------------------------------------------
__global__ __launch_bounds__(256, 4)
void topk_warp(const float* __restrict__ A, const float* __restrict__ W,
               const float* __restrict__ bias, float* __restrict__ out) {
    const int lane  = threadIdx.x & 31;
    const int wslot = threadIdx.x >> 5;
    const int token = blockIdx.x * 8 + wslot;
    const float* row = g_logits + (size_t)token * EXPERTS;

    __shared__ float s_cb[8][NCAND];
    __shared__ float s_cs[8][NCAND];
    __shared__ int   s_ce[8][NCAND];

    float b[24];
    #pragma unroll
    for (int j = 0; j < 24; j++) b[j] = row[j * 32 + lane];

    float m = b[0];
    #pragma unroll
    for (int j = 1; j < 24; j++) m = fmaxf(m, b[j]);
    #pragma unroll
    for (int off = 16; off; off >>= 1) m = fmaxf(m, __shfl_xor_sync(0xffffffffu, m, off));
    float ssum = 0.0f;
    #pragma unroll
    for (int j = 0; j < 24; j++) { b[j] = expf(b[j] - m); ssum += b[j]; }
    #pragma unroll
    for (int off = 16; off; off >>= 1) ssum += __shfl_xor_sync(0xffffffffu, ssum, off);
    const float inv = 1.0f / ssum;
    #pragma unroll
    for (int j = 0; j < 24; j++) b[j] = fmaf(b[j], inv, __ldg(&bias[j * 32 + lane]));

    for (int sel = 0; sel < NCAND; sel++) {
        float v = b[0]; int je = 0;
        #pragma unroll
        for (int j = 1; j < 24; j++) if (b[j] > v) { v = b[j]; je = j; }
        int idx = je * 32 + lane;
        #pragma unroll
        for (int off = 16; off; off >>= 1) {
            float ov = __shfl_xor_sync(0xffffffffu, v,   off);
            int   oi = __shfl_xor_sync(0xffffffffu, idx, off);
            if (ov > v || (ov == v && oi < idx)) { v = ov; idx = oi; }
        }
        if ((idx & 31) == lane) {
            const int jw = idx >> 5;
            #pragma unroll
            for (int j = 0; j < 24; j++) if (j == jw) b[j] = -CUDART_INF_F;
        }
        if (lane == 0) {
            s_cb[wslot][sel] = v;
            s_cs[wslot][sel] = v - __ldg(&bias[idx]);
            s_ce[wslot][sel] = idx;
        }
    }
    __syncwarp();

    unsigned fmask = 0;
    #pragma unroll
    for (int r = 0; r < NCAND - 1; r++)
        if (s_cb[wslot][r] - s_cb[wslot][r + 1] < TAU) fmask |= (3u << r);

    const float* x = A + (size_t)token * HIDDEN;
    while (fmask) {
        const int r = __ffs(fmask) - 1;
        fmask &= fmask - 1;
        const int e = s_ce[wslot][r];
        const float* w = W + (size_t)e * HIDDEN;
        float p = 0.0f;
        #pragma unroll 8
        for (int jj = lane; jj < HIDDEN; jj += 32)
            p = fmaf(x[jj], w[jj], p);
        #pragma unroll
        for (int off = 16; off; off >>= 1)
            p += __shfl_xor_sync(0xffffffffu, p, off);
        if (lane == 0) {
            const float sn = expf(p - m) * inv;
            s_cs[wslot][r] = sn;
            s_cb[wslot][r] = sn + __ldg(&bias[e]);
        }
    }
    __syncwarp();

    if (lane < NCAND) {
        const float mv = s_cb[wslot][lane];
        const int   me = s_ce[wslot][lane];
        int rank = 0;
        #pragma unroll
        for (int j = 0; j < NCAND; j++) {
            const float jv = s_cb[wslot][j];
            const int   jee = s_ce[wslot][j];
            if (jv > mv || (jv == mv && jee < me)) rank++;
        }
        if (rank < TOPK) {
            out[(size_t)token * TOPK + rank]                         = (float)me;
            out[(size_t)TOKENS * TOPK + (size_t)token * TOPK + rank] = s_cs[wslot][lane] * RSCALE;
        }
    }
}

extern "C" void kernel_launch(void* const* d_in, const int* in_sizes, int n_in,
                              void* d_out, int out_size) {
    const float* A    = (const float*)d_in[0];
    const float* W    = (const float*)d_in[1];
    const float* bias = (const float*)d_in[2];
    float* out = (float*)d_out;

    __half* dWh = nullptr;
    cudaGetSymbolAddress((void**)&dWh, g_Wh);

    cvt_kernel<<<512, 256>>>((const float4*)W, (uint2*)dWh, EXPERTS * HIDDEN / 4);

    cudaFuncSetAttribute(router_gemm_fused, cudaFuncAttributeMaxDynamicSharedMemorySize, GEMM_SMEM);
    router_gemm_fused<<<GRID, 256, GEMM_SMEM>>>(A);

    topk_warp<<<TOKENS / 8, 256>>>(A, W, bias, out);
}

// round 11
// speedup vs baseline: 1.2326x; 1.2326x over previous
#include <cuda_runtime.h>
#include <cuda_fp16.h>
#include <math_constants.h>
#include <cstdint>

#define TOKENS  8192
#define HIDDEN  6144
#define EXPERTS 768
#define TOPK    12
#define NCAND   13
#define RSCALE  2.5f
#define TAU     1e-4f

// ---------------- GEMM config ----------------
#define BM 64
#define BN 128
#define BK 64                    // fp16 elems per stage row = 128 B (SW128 atom)
#define NSTAGES (HIDDEN / BK)    // 96
#define RING 3
#define ATILE_B (BM * 128)       // 8192
#define BTILE_B (BN * 128)       // 16384
#define STAGE_B (ATILE_B + BTILE_B)      // 24576
#define GEMM_SMEM (RING * STAGE_B)       // 73728

__device__ __half g_Ah[(size_t)TOKENS * HIDDEN];    // 96 MB
__device__ __half g_Wh[(size_t)EXPERTS * HIDDEN];   // 9 MB
__device__ float  g_logits[(size_t)TOKENS * EXPERTS];

// ---------------- helpers ----------------
__device__ __forceinline__ uint32_t smem_u32(const void* p) {
    uint32_t a;
    asm("{ .reg .u64 t; cvta.to.shared.u64 t, %1; cvt.u32.u64 %0, t; }" : "=r"(a) : "l"(p));
    return a;
}
__device__ __forceinline__ uint2 f4_to_h4(float4 v) {
    __half2 p0 = __floats2half2_rn(v.x, v.y);
    __half2 p1 = __floats2half2_rn(v.z, v.w);
    return make_uint2(*(uint32_t*)&p0, *(uint32_t*)&p1);
}
__device__ __forceinline__ void cp16(uint32_t dst, const void* src) {
    asm volatile("cp.async.cg.shared.global [%0], [%1], 16;" :: "r"(dst), "l"(src) : "memory");
}
#define CP_COMMIT() asm volatile("cp.async.commit_group;" ::: "memory")
#define CP_WAIT1()  asm volatile("cp.async.wait_group 1;" ::: "memory")

__device__ __forceinline__ void ldm_x4(uint32_t* r, uint32_t addr) {
    asm volatile("ldmatrix.sync.aligned.m8n8.x4.shared.b16 {%0,%1,%2,%3}, [%4];"
                 : "=r"(r[0]), "=r"(r[1]), "=r"(r[2]), "=r"(r[3]) : "r"(addr));
}
__device__ __forceinline__ void mma16(float* c, const uint32_t* a, const uint32_t* b) {
    asm volatile(
        "mma.sync.aligned.m16n8k16.row.col.f32.f16.f16.f32 "
        "{%0,%1,%2,%3}, {%4,%5,%6,%7}, {%8,%9}, {%0,%1,%2,%3};"
        : "+f"(c[0]), "+f"(c[1]), "+f"(c[2]), "+f"(c[3])
        : "r"(a[0]), "r"(a[1]), "r"(a[2]), "r"(a[3]), "r"(b[0]), "r"(b[1]));
}
__device__ __forceinline__ uint32_t swz(int row, int ch) {
    return (uint32_t)(row * 128 + ((ch ^ (row & 7)) << 4));
}

// ---------------------------------------------------------------------------
// fp32 -> fp16, 4 independent float4 per thread (MLP>=4). Grid sized exactly.
// ---------------------------------------------------------------------------
__global__ __launch_bounds__(256)
void cvt4_kernel(const float4* __restrict__ in, uint2* __restrict__ out, int n4) {
    const int base   = blockIdx.x * blockDim.x + threadIdx.x;
    const int stride = gridDim.x * blockDim.x;
    float4 v0 = in[base];
    float4 v1 = in[base + stride];
    float4 v2 = in[base + 2 * stride];
    float4 v3 = in[base + 3 * stride];
    out[base]              = f4_to_h4(v0);
    out[base + stride]     = f4_to_h4(v1);
    out[base + 2 * stride] = f4_to_h4(v2);
    out[base + 3 * stride] = f4_to_h4(v3);
}

// ---------------------------------------------------------------------------
// fp16 GEMM, cp.async ring-3, SW128 smem. BM=64: 8 warps 2(m) x 4(n),
// warp tile 32x32, 3 CTAs/SM.
// ---------------------------------------------------------------------------
__global__ __launch_bounds__(256, 3)
void router_gemm_cp() {
    extern __shared__ char smem[];
    const uint32_t smbase = smem_u32(smem);

    const int tid  = threadIdx.x;
    const int wid  = tid >> 5;
    const int lane = tid & 31;
    const int m0 = blockIdx.y * BM;
    const int n0 = blockIdx.x * BN;

    const int wm = wid & 1;    // 32-row band
    const int wn = wid >> 1;   // 32-col band

    // writer maps (16B chunks, 8 per row):
    // A: 512 chunks -> 2/thread; B: 1024 chunks -> 4/thread.
    const int wrow = tid >> 3;   // + 32*i
    const int wc   = tid & 7;

    const __half* Abase = g_Ah + (size_t)m0 * HIDDEN;
    const __half* Bbase = g_Wh + (size_t)n0 * HIDDEN;

    float acc[2][4][4];
    #pragma unroll
    for (int mi = 0; mi < 2; mi++)
        #pragma unroll
        for (int ni = 0; ni < 4; ni++)
            #pragma unroll
            for (int j = 0; j < 4; j++) acc[mi][ni][j] = 0.0f;

    auto issue = [&](int s) {
        const uint32_t slot = smbase + (s % RING) * STAGE_B;
        const __half* ga = Abase + s * BK;
        const __half* gb = Bbase + s * BK;
        #pragma unroll
        for (int i = 0; i < 2; i++)
            cp16(slot + swz(wrow + 32 * i, wc),
                 ga + (size_t)(wrow + 32 * i) * HIDDEN + wc * 8);
        #pragma unroll
        for (int i = 0; i < 4; i++)
            cp16(slot + ATILE_B + swz(wrow + 32 * i, wc),
                 gb + (size_t)(wrow + 32 * i) * HIDDEN + wc * 8);
    };

    issue(0); CP_COMMIT();
    issue(1); CP_COMMIT();

    // fragment address components
    const int a_row = wm * 32 + (lane & 7) + ((lane >> 3) & 1) * 8;  // + mi*16
    const int a_chl = (lane >> 4) & 1;                                // + w*2
    const int b_row = wn * 32 + (lane & 7) + ((lane >> 4) & 1) * 8;  // + p*16
    const int b_chl = (lane >> 3) & 1;                                // + w*2

    for (int s = 0; s < NSTAGES; s++) {
        CP_WAIT1();
        __syncthreads();
        if (s + 2 < NSTAGES) issue(s + 2);
        CP_COMMIT();

        const uint32_t sA = smbase + (s % RING) * STAGE_B;
        const uint32_t sB = sA + ATILE_B;

        #pragma unroll
        for (int w = 0; w < 4; w++) {        // four k16 windows of BK=64
            uint32_t af[2][4], bf[2][4];
            #pragma unroll
            for (int mi = 0; mi < 2; mi++)
                ldm_x4(af[mi], sA + swz(a_row + mi * 16, w * 2 + a_chl));
            #pragma unroll
            for (int p = 0; p < 2; p++)
                ldm_x4(bf[p], sB + swz(b_row + p * 16, w * 2 + b_chl));
            #pragma unroll
            for (int mi = 0; mi < 2; mi++) {
                mma16(acc[mi][0], af[mi], &bf[0][0]);
                mma16(acc[mi][1], af[mi], &bf[0][2]);
                mma16(acc[mi][2], af[mi], &bf[1][0]);
                mma16(acc[mi][3], af[mi], &bf[1][2]);
            }
        }
        __syncthreads();
    }

    #pragma unroll
    for (int mi = 0; mi < 2; mi++) {
        const int row = m0 + wm * 32 + mi * 16 + (lane >> 2);
        #pragma unroll
        for (int ni = 0; ni < 4; ni++) {
            const int col = n0 + wn * 32 + ni * 8 + (lane & 3) * 2;
            *(float2*)(g_logits + (size_t)row * EXPERTS + col)       = make_float2(acc[mi][ni][0], acc[mi][ni][1]);
            *(float2*)(g_logits + (size_t)(row + 8) * EXPERTS + col) = make_float2(acc[mi][ni][2], acc[mi][ni][3]);
        }
    }
}

// ---------------------------------------------------------------------------
// Warp-per-token topk (unchanged from R9 — frozen for attribution).
// ---------------------------------------------------------------------------
__global__ __launch_bounds__(256, 4)
void topk_warp(const float* __restrict__ A, const float* __restrict__ W,
               const float* __restrict__ bias, float* __restrict__ out) {
    const int lane  = threadIdx.x & 31;
    const int wslot = threadIdx.x >> 5;
    const int token = blockIdx.x * 8 + wslot;
    const float* row = g_logits + (size_t)token * EXPERTS;

    __shared__ float s_cb[8][NCAND];
    __shared__ float s_cs[8][NCAND];
    __shared__ int   s_ce[8][NCAND];

    float b[24];
    #pragma unroll
    for (int j = 0; j < 24; j++) b[j] = row[j * 32 + lane];

    float m = b[0];
    #pragma unroll
    for (int j = 1; j < 24; j++) m = fmaxf(m, b[j]);
    #pragma unroll
    for (int off = 16; off; off >>= 1) m = fmaxf(m, __shfl_xor_sync(0xffffffffu, m, off));
    float ssum = 0.0f;
    #pragma unroll
    for (int j = 0; j < 24; j++) { b[j] = expf(b[j] - m); ssum += b[j]; }
    #pragma unroll
    for (int off = 16; off; off >>= 1) ssum += __shfl_xor_sync(0xffffffffu, ssum, off);
    const float inv = 1.0f / ssum;
    #pragma unroll
    for (int j = 0; j < 24; j++) b[j] = fmaf(b[j], inv, __ldg(&bias[j * 32 + lane]));

    for (int sel = 0; sel < NCAND; sel++) {
        float v = b[0]; int je = 0;
        #pragma unroll
        for (int j = 1; j < 24; j++) if (b[j] > v) { v = b[j]; je = j; }
        int idx = je * 32 + lane;
        #pragma unroll
        for (int off = 16; off; off >>= 1) {
            float ov = __shfl_xor_sync(0xffffffffu, v,   off);
            int   oi = __shfl_xor_sync(0xffffffffu, idx, off);
            if (ov > v || (ov == v && oi < idx)) { v = ov; idx = oi; }
        }
        if ((idx & 31) == lane) {
            const int jw = idx >> 5;
            #pragma unroll
            for (int j = 0; j < 24; j++) if (j == jw) b[j] = -CUDART_INF_F;
        }
        if (lane == 0) {
            s_cb[wslot][sel] = v;
            s_cs[wslot][sel] = v - __ldg(&bias[idx]);
            s_ce[wslot][sel] = idx;
        }
    }
    __syncwarp();

    unsigned fmask = 0;
    #pragma unroll
    for (int r = 0; r < NCAND - 1; r++)
        if (s_cb[wslot][r] - s_cb[wslot][r + 1] < TAU) fmask |= (3u << r);

    const float* x = A + (size_t)token * HIDDEN;
    while (fmask) {
        const int r = __ffs(fmask) - 1;
        fmask &= fmask - 1;
        const int e = s_ce[wslot][r];
        const float* w = W + (size_t)e * HIDDEN;
        float p = 0.0f;
        #pragma unroll 8
        for (int jj = lane; jj < HIDDEN; jj += 32)
            p = fmaf(x[jj], w[jj], p);
        #pragma unroll
        for (int off = 16; off; off >>= 1)
            p += __shfl_xor_sync(0xffffffffu, p, off);
        if (lane == 0) {
            const float sn = expf(p - m) * inv;
            s_cs[wslot][r] = sn;
            s_cb[wslot][r] = sn + __ldg(&bias[e]);
        }
    }
    __syncwarp();

    if (lane < NCAND) {
        const float mv = s_cb[wslot][lane];
        const int   me = s_ce[wslot][lane];
        int rank = 0;
        #pragma unroll
        for (int j = 0; j < NCAND; j++) {
            const float jv = s_cb[wslot][j];
            const int   jee = s_ce[wslot][j];
            if (jv > mv || (jv == mv && jee < me)) rank++;
        }
        if (rank < TOPK) {
            out[(size_t)token * TOPK + rank]                         = (float)me;
            out[(size_t)TOKENS * TOPK + (size_t)token * TOPK + rank] = s_cs[wslot][lane] * RSCALE;
        }
    }
}

extern "C" void kernel_launch(void* const* d_in, const int* in_sizes, int n_in,
                              void* d_out, int out_size) {
    const float* A    = (const float*)d_in[0];
    const float* W    = (const float*)d_in[1];
    const float* bias = (const float*)d_in[2];
    float* out = (float*)d_out;

    __half* dAh = nullptr; __half* dWh = nullptr;
    cudaGetSymbolAddress((void**)&dAh, g_Ah);
    cudaGetSymbolAddress((void**)&dWh, g_Wh);

    // exact grids: A: 12582912 f4 / (256*4) = 12288 blocks; W: 1179648 / 1024 = 1152
    cvt4_kernel<<<12288, 256>>>((const float4*)A, (uint2*)dAh, TOKENS * HIDDEN / 4);
    cvt4_kernel<<<1152, 256>>>((const float4*)W, (uint2*)dWh, EXPERTS * HIDDEN / 4);

    cudaFuncSetAttribute(router_gemm_cp, cudaFuncAttributeMaxDynamicSharedMemorySize, GEMM_SMEM);
    dim3 grid(EXPERTS / BN, TOKENS / BM);   // (6, 128): x-fastest, 6 CTAs share each A block
    router_gemm_cp<<<grid, 256, GEMM_SMEM>>>();

    topk_warp<<<TOKENS / 8, 256>>>(A, W, bias, out);
}

// round 12
// speedup vs baseline: 1.2957x; 1.0512x over previous
#include <cuda_runtime.h>
#include <cuda_fp16.h>
#include <math_constants.h>
#include <cstdint>

#define TOKENS  8192
#define HIDDEN  6144
#define EXPERTS 768
#define TOPK    12
#define NCAND   13
#define RSCALE  2.5f
#define TAU     1e-4f

// ---------------- GEMM config (R9 known-best) ----------------
#define BM 128
#define BN 128
#define BK 64
#define NSTAGES (HIDDEN / BK)    // 96
#define RING 3
#define TILE_B  (BM * 128)       // 16384
#define STAGE_B (2 * TILE_B)
#define GEMM_SMEM (RING * STAGE_B)  // 98304

__device__ __half g_Ah[(size_t)TOKENS * HIDDEN];
__device__ __half g_Wh[(size_t)EXPERTS * HIDDEN];
__device__ float  g_logits[(size_t)TOKENS * EXPERTS];

// ---------------- helpers ----------------
__device__ __forceinline__ uint32_t smem_u32(const void* p) {
    uint32_t a;
    asm("{ .reg .u64 t; cvta.to.shared.u64 t, %1; cvt.u32.u64 %0, t; }" : "=r"(a) : "l"(p));
    return a;
}
__device__ __forceinline__ uint2 f4_to_h4(float4 v) {
    __half2 p0 = __floats2half2_rn(v.x, v.y);
    __half2 p1 = __floats2half2_rn(v.z, v.w);
    return make_uint2(*(uint32_t*)&p0, *(uint32_t*)&p1);
}
__device__ __forceinline__ void cp16(uint32_t dst, const void* src) {
    asm volatile("cp.async.cg.shared.global [%0], [%1], 16;" :: "r"(dst), "l"(src) : "memory");
}
#define CP_COMMIT() asm volatile("cp.async.commit_group;" ::: "memory")
#define CP_WAIT1()  asm volatile("cp.async.wait_group 1;" ::: "memory")

__device__ __forceinline__ void ldm_x4(uint32_t* r, uint32_t addr) {
    asm volatile("ldmatrix.sync.aligned.m8n8.x4.shared.b16 {%0,%1,%2,%3}, [%4];"
                 : "=r"(r[0]), "=r"(r[1]), "=r"(r[2]), "=r"(r[3]) : "r"(addr));
}
__device__ __forceinline__ void mma16(float* c, const uint32_t* a, const uint32_t* b) {
    asm volatile(
        "mma.sync.aligned.m16n8k16.row.col.f32.f16.f16.f32 "
        "{%0,%1,%2,%3}, {%4,%5,%6,%7}, {%8,%9}, {%0,%1,%2,%3};"
        : "+f"(c[0]), "+f"(c[1]), "+f"(c[2]), "+f"(c[3])
        : "r"(a[0]), "r"(a[1]), "r"(a[2]), "r"(a[3]), "r"(b[0]), "r"(b[1]));
}
__device__ __forceinline__ uint32_t swz(int row, int ch) {
    return (uint32_t)(row * 128 + ((ch ^ (row & 7)) << 4));
}
// order-preserving float <-> u32 bijection (total order, handles negatives)
__device__ __forceinline__ uint32_t fkey(float x) {
    uint32_t u = __float_as_uint(x);
    return (u & 0x80000000u) ? ~u : (u | 0x80000000u);
}
__device__ __forceinline__ float fval(uint32_t k) {
    uint32_t u = (k & 0x80000000u) ? (k & 0x7FFFFFFFu) : ~k;
    return __uint_as_float(u);
}

// ---------------------------------------------------------------------------
// fp32 -> fp16, 4 independent float4 per thread. Exact grids.
// ---------------------------------------------------------------------------
__global__ __launch_bounds__(256)
void cvt4_kernel(const float4* __restrict__ in, uint2* __restrict__ out, int n4) {
    const int base   = blockIdx.x * blockDim.x + threadIdx.x;
    const int stride = gridDim.x * blockDim.x;
    float4 v0 = in[base];
    float4 v1 = in[base + stride];
    float4 v2 = in[base + 2 * stride];
    float4 v3 = in[base + 3 * stride];
    out[base]              = f4_to_h4(v0);
    out[base + stride]     = f4_to_h4(v1);
    out[base + 2 * stride] = f4_to_h4(v2);
    out[base + 3 * stride] = f4_to_h4(v3);
}

// ---------------------------------------------------------------------------
// fp16 GEMM, cp.async ring-3, SW128 smem (R9 exact).
// ---------------------------------------------------------------------------
__global__ __launch_bounds__(256, 2)
void router_gemm_cp() {
    extern __shared__ char smem[];
    const uint32_t smbase = smem_u32(smem);

    const int tid  = threadIdx.x;
    const int wid  = tid >> 5;
    const int lane = tid & 31;
    const int m0 = blockIdx.y * BM;
    const int n0 = blockIdx.x * BN;

    const int wm = wid & 1;
    const int wn = wid >> 1;

    const int wrow = tid >> 3;
    const int wc   = tid & 7;

    const __half* Abase = g_Ah + (size_t)m0 * HIDDEN;
    const __half* Bbase = g_Wh + (size_t)n0 * HIDDEN;

    float acc[4][4][4];
    #pragma unroll
    for (int mi = 0; mi < 4; mi++)
        #pragma unroll
        for (int ni = 0; ni < 4; ni++)
            #pragma unroll
            for (int j = 0; j < 4; j++) acc[mi][ni][j] = 0.0f;

    auto issue = [&](int s) {
        const uint32_t slot = smbase + (s % RING) * STAGE_B;
        const __half* ga = Abase + s * BK;
        const __half* gb = Bbase + s * BK;
        #pragma unroll
        for (int i = 0; i < 4; i++) {
            const int row = wrow + 32 * i;
            const uint32_t so = swz(row, wc);
            cp16(slot + so,          ga + (size_t)row * HIDDEN + wc * 8);
            cp16(slot + TILE_B + so, gb + (size_t)row * HIDDEN + wc * 8);
        }
    };

    issue(0); CP_COMMIT();
    issue(1); CP_COMMIT();

    const int a_row = wm * 64 + (lane & 7) + ((lane >> 3) & 1) * 8;
    const int a_chl = (lane >> 4) & 1;
    const int b_row = wn * 32 + (lane & 7) + ((lane >> 4) & 1) * 8;
    const int b_chl = (lane >> 3) & 1;

    for (int s = 0; s < NSTAGES; s++) {
        CP_WAIT1();
        __syncthreads();
        if (s + 2 < NSTAGES) issue(s + 2);
        CP_COMMIT();

        const uint32_t sA = smbase + (s % RING) * STAGE_B;
        const uint32_t sB = sA + TILE_B;

        #pragma unroll
        for (int w = 0; w < 4; w++) {
            uint32_t af[4][4], bf[2][4];
            #pragma unroll
            for (int mi = 0; mi < 4; mi++)
                ldm_x4(af[mi], sA + swz(a_row + mi * 16, w * 2 + a_chl));
            #pragma unroll
            for (int p = 0; p < 2; p++)
                ldm_x4(bf[p], sB + swz(b_row + p * 16, w * 2 + b_chl));
            #pragma unroll
            for (int mi = 0; mi < 4; mi++) {
                mma16(acc[mi][0], af[mi], &bf[0][0]);
                mma16(acc[mi][1], af[mi], &bf[0][2]);
                mma16(acc[mi][2], af[mi], &bf[1][0]);
                mma16(acc[mi][3], af[mi], &bf[1][2]);
            }
        }
        __syncthreads();
    }

    #pragma unroll
    for (int mi = 0; mi < 4; mi++) {
        const int row = m0 + wm * 64 + mi * 16 + (lane >> 2);
        #pragma unroll
        for (int ni = 0; ni < 4; ni++) {
            const int col = n0 + wn * 32 + ni * 8 + (lane & 3) * 2;
            *(float2*)(g_logits + (size_t)row * EXPERTS + col)       = make_float2(acc[mi][ni][0], acc[mi][ni][1]);
            *(float2*)(g_logits + (size_t)(row + 8) * EXPERTS + col) = make_float2(acc[mi][ni][2], acc[mi][ni][3]);
        }
    }
}

// ---------------------------------------------------------------------------
// Warp-per-token topk with redux-based argmax rounds.
// 4 warps/block, grid 2048.
// ---------------------------------------------------------------------------
__global__ __launch_bounds__(128, 8)
void topk_warp(const float* __restrict__ A, const float* __restrict__ W,
               const float* __restrict__ bias, float* __restrict__ out) {
    const int lane  = threadIdx.x & 31;
    const int wslot = threadIdx.x >> 5;            // 0..3
    const int token = blockIdx.x * 4 + wslot;
    const float* row = g_logits + (size_t)token * EXPERTS;

    __shared__ float s_cb[4][NCAND];
    __shared__ float s_cs[4][NCAND];
    __shared__ int   s_ce[4][NCAND];

    float b[24];
    #pragma unroll
    for (int j = 0; j < 24; j++) b[j] = row[j * 32 + lane];

    // softmax stats
    float m = b[0];
    #pragma unroll
    for (int j = 1; j < 24; j++) m = fmaxf(m, b[j]);
    #pragma unroll
    for (int off = 16; off; off >>= 1) m = fmaxf(m, __shfl_xor_sync(0xffffffffu, m, off));
    float ssum = 0.0f;
    #pragma unroll
    for (int j = 0; j < 24; j++) { b[j] = expf(b[j] - m); ssum += b[j]; }
    #pragma unroll
    for (int off = 16; off; off >>= 1) ssum += __shfl_xor_sync(0xffffffffu, ssum, off);
    const float inv = 1.0f / ssum;
    #pragma unroll
    for (int j = 0; j < 24; j++) b[j] = fmaf(b[j], inv, __ldg(&bias[j * 32 + lane]));

    // 13 redux-based selection rounds (tie -> lowest expert index)
    for (int sel = 0; sel < NCAND; sel++) {
        // parallel fmax tree over 24 regs
        float t12[12];
        #pragma unroll
        for (int j = 0; j < 12; j++) t12[j] = fmaxf(b[2 * j], b[2 * j + 1]);
        float t6[6];
        #pragma unroll
        for (int j = 0; j < 6; j++) t6[j] = fmaxf(t12[2 * j], t12[2 * j + 1]);
        float t3a = fmaxf(t6[0], t6[1]), t3b = fmaxf(t6[2], t6[3]), t3c = fmaxf(t6[4], t6[5]);
        const float v = fmaxf(fmaxf(t3a, t3b), t3c);

        // warp max via integer redux on order-preserving key
        const uint32_t gk = __reduce_max_sync(0xffffffffu, fkey(v));
        const float vg = fval(gk);

        // index recovery: bitmask of matching slots, min expert idx via redux
        uint32_t msk = 0;
        #pragma unroll
        for (int j = 0; j < 24; j++) msk |= (b[j] == vg) ? (1u << j) : 0u;
        const uint32_t cand = msk ? (uint32_t)((__ffs(msk) - 1) * 32 + lane) : 0xFFFFFFFFu;
        const uint32_t idx = __reduce_min_sync(0xffffffffu, cand);

        if ((idx & 31u) == (uint32_t)lane) {
            const int jw = idx >> 5;
            #pragma unroll
            for (int j = 0; j < 24; j++) if (j == jw) b[j] = -CUDART_INF_F;
        }
        if (lane == 0) {
            s_cb[wslot][sel] = vg;
            s_cs[wslot][sel] = vg - __ldg(&bias[idx]);
            s_ce[wslot][sel] = (int)idx;
        }
    }
    __syncwarp();

    // flag tight adjacent pairs
    unsigned fmask = 0;
    #pragma unroll
    for (int r = 0; r < NCAND - 1; r++)
        if (s_cb[wslot][r] - s_cb[wslot][r + 1] < TAU) fmask |= (3u << r);

    // exact fp32 rescore of flagged candidates
    const float* x = A + (size_t)token * HIDDEN;
    while (fmask) {
        const int r = __ffs(fmask) - 1;
        fmask &= fmask - 1;
        const int e = s_ce[wslot][r];
        const float* w = W + (size_t)e * HIDDEN;
        float p = 0.0f;
        #pragma unroll 8
        for (int jj = lane; jj < HIDDEN; jj += 32)
            p = fmaf(x[jj], w[jj], p);
        #pragma unroll
        for (int off = 16; off; off >>= 1)
            p += __shfl_xor_sync(0xffffffffu, p, off);
        if (lane == 0) {
            const float sn = expf(p - m) * inv;
            s_cs[wslot][r] = sn;
            s_cb[wslot][r] = sn + __ldg(&bias[e]);
        }
    }
    __syncwarp();

    // rank-based parallel output
    if (lane < NCAND) {
        const float mv = s_cb[wslot][lane];
        const int   me = s_ce[wslot][lane];
        int rank = 0;
        #pragma unroll
        for (int j = 0; j < NCAND; j++) {
            const float jv = s_cb[wslot][j];
            const int   je = s_ce[wslot][j];
            if (jv > mv || (jv == mv && je < me)) rank++;
        }
        if (rank < TOPK) {
            out[(size_t)token * TOPK + rank]                         = (float)me;
            out[(size_t)TOKENS * TOPK + (size_t)token * TOPK + rank] = s_cs[wslot][lane] * RSCALE;
        }
    }
}

extern "C" void kernel_launch(void* const* d_in, const int* in_sizes, int n_in,
                              void* d_out, int out_size) {
    const float* A    = (const float*)d_in[0];
    const float* W    = (const float*)d_in[1];
    const float* bias = (const float*)d_in[2];
    float* out = (float*)d_out;

    __half* dAh = nullptr; __half* dWh = nullptr;
    cudaGetSymbolAddress((void**)&dAh, g_Ah);
    cudaGetSymbolAddress((void**)&dWh, g_Wh);

    cvt4_kernel<<<12288, 256>>>((const float4*)A, (uint2*)dAh, TOKENS * HIDDEN / 4);
    cvt4_kernel<<<1152, 256>>>((const float4*)W, (uint2*)dWh, EXPERTS * HIDDEN / 4);

    cudaFuncSetAttribute(router_gemm_cp, cudaFuncAttributeMaxDynamicSharedMemorySize, GEMM_SMEM);
    dim3 grid(EXPERTS / BN, TOKENS / BM);   // (6, 64)
    router_gemm_cp<<<grid, 256, GEMM_SMEM>>>();

    topk_warp<<<TOKENS / 4, 128>>>(A, W, bias, out);
}

// round 13
// speedup vs baseline: 1.3097x; 1.0108x over previous
#include <cuda_runtime.h>
#include <cuda_fp16.h>
#include <math_constants.h>
#include <cstdint>

#define TOKENS  8192
#define HIDDEN  6144
#define EXPERTS 768
#define TOPK    12
#define NCAND   13
#define RSCALE  2.5f
#define TAU     1e-4f

// ---------------- GEMM config ----------------
#define BM 128
#define BN 128
#define BK 64
#define NSTAGES (HIDDEN / BK)    // 96
#define RING 3
#define TILE_B  (BM * 128)       // 16384
#define STAGE_B (2 * TILE_B)
#define GEMM_SMEM (RING * STAGE_B)  // 98304

#define NA4 (TOKENS * HIDDEN / 4)    // 12582912
#define NW4 (EXPERTS * HIDDEN / 4)   // 1179648
#define CVT_BLOCKS ((NA4 + NW4) / (256 * 4))   // 13440 exact

__device__ __half g_Ah[(size_t)TOKENS * HIDDEN];
__device__ __half g_Wh[(size_t)EXPERTS * HIDDEN];
__device__ float  g_logits[(size_t)TOKENS * EXPERTS];

// ---------------- helpers ----------------
__device__ __forceinline__ uint32_t smem_u32(const void* p) {
    uint32_t a;
    asm("{ .reg .u64 t; cvta.to.shared.u64 t, %1; cvt.u32.u64 %0, t; }" : "=r"(a) : "l"(p));
    return a;
}
__device__ __forceinline__ uint2 f4_to_h4(float4 v) {
    __half2 p0 = __floats2half2_rn(v.x, v.y);
    __half2 p1 = __floats2half2_rn(v.z, v.w);
    return make_uint2(*(uint32_t*)&p0, *(uint32_t*)&p1);
}
__device__ __forceinline__ void cp16(uint32_t dst, const void* src) {
    asm volatile("cp.async.cg.shared.global [%0], [%1], 16;" :: "r"(dst), "l"(src) : "memory");
}
#define CP_COMMIT() asm volatile("cp.async.commit_group;" ::: "memory")
#define CP_WAIT1()  asm volatile("cp.async.wait_group 1;" ::: "memory")

__device__ __forceinline__ void ldm_x4(uint32_t* r, uint32_t addr) {
    asm volatile("ldmatrix.sync.aligned.m8n8.x4.shared.b16 {%0,%1,%2,%3}, [%4];"
                 : "=r"(r[0]), "=r"(r[1]), "=r"(r[2]), "=r"(r[3]) : "r"(addr));
}
__device__ __forceinline__ void mma16(float* c, const uint32_t* a, const uint32_t* b) {
    asm volatile(
        "mma.sync.aligned.m16n8k16.row.col.f32.f16.f16.f32 "
        "{%0,%1,%2,%3}, {%4,%5,%6,%7}, {%8,%9}, {%0,%1,%2,%3};"
        : "+f"(c[0]), "+f"(c[1]), "+f"(c[2]), "+f"(c[3])
        : "r"(a[0]), "r"(a[1]), "r"(a[2]), "r"(a[3]), "r"(b[0]), "r"(b[1]));
}
__device__ __forceinline__ uint32_t swz(int row, int ch) {
    return (uint32_t)(row * 128 + ((ch ^ (row & 7)) << 4));
}
// order-preserving float <-> u32 bijection
__device__ __forceinline__ uint32_t fkey(float x) {
    uint32_t u = __float_as_uint(x);
    return (u & 0x80000000u) ? ~u : (u | 0x80000000u);
}
__device__ __forceinline__ float fval(uint32_t k) {
    uint32_t u = (k & 0x80000000u) ? (k & 0x7FFFFFFFu) : ~k;
    return __uint_as_float(u);
}

// ---------------------------------------------------------------------------
// Merged fp32->fp16 conversion: linear index < NA4 -> A, else W. Exact grid.
// ---------------------------------------------------------------------------
__global__ __launch_bounds__(256)
void cvt_all_kernel(const float4* __restrict__ inA, const float4* __restrict__ inW,
                    uint2* __restrict__ outA, uint2* __restrict__ outW) {
    const int base   = blockIdx.x * blockDim.x + threadIdx.x;
    const int stride = gridDim.x * blockDim.x;   // 3,440,640
    #pragma unroll
    for (int k = 0; k < 4; k++) {
        const int i = base + k * stride;
        if (i < NA4) outA[i] = f4_to_h4(inA[i]);
        else         outW[i - NA4] = f4_to_h4(inW[i - NA4]);
    }
}

// ---------------------------------------------------------------------------
// fp16 GEMM, cp.async ring-3, SW128 smem. ONE sync per stage (trailing sync
// proved redundant: compute(s) precedes each thread's next-iter sync, which
// precedes any issue(s+3) into slot s%3).
// ---------------------------------------------------------------------------
__global__ __launch_bounds__(256, 2)
void router_gemm_cp() {
    extern __shared__ char smem[];
    const uint32_t smbase = smem_u32(smem);

    const int tid  = threadIdx.x;
    const int wid  = tid >> 5;
    const int lane = tid & 31;
    const int m0 = blockIdx.y * BM;
    const int n0 = blockIdx.x * BN;

    const int wm = wid & 1;
    const int wn = wid >> 1;

    const int wrow = tid >> 3;
    const int wc   = tid & 7;

    const __half* Abase = g_Ah + (size_t)m0 * HIDDEN;
    const __half* Bbase = g_Wh + (size_t)n0 * HIDDEN;

    float acc[4][4][4];
    #pragma unroll
    for (int mi = 0; mi < 4; mi++)
        #pragma unroll
        for (int ni = 0; ni < 4; ni++)
            #pragma unroll
            for (int j = 0; j < 4; j++) acc[mi][ni][j] = 0.0f;

    auto issue = [&](int s) {
        const uint32_t slot = smbase + (s % RING) * STAGE_B;
        const __half* ga = Abase + s * BK;
        const __half* gb = Bbase + s * BK;
        #pragma unroll
        for (int i = 0; i < 4; i++) {
            const int row = wrow + 32 * i;
            const uint32_t so = swz(row, wc);
            cp16(slot + so,          ga + (size_t)row * HIDDEN + wc * 8);
            cp16(slot + TILE_B + so, gb + (size_t)row * HIDDEN + wc * 8);
        }
    };

    issue(0); CP_COMMIT();
    issue(1); CP_COMMIT();

    const int a_row = wm * 64 + (lane & 7) + ((lane >> 3) & 1) * 8;
    const int a_chl = (lane >> 4) & 1;
    const int b_row = wn * 32 + (lane & 7) + ((lane >> 4) & 1) * 8;
    const int b_chl = (lane >> 3) & 1;

    for (int s = 0; s < NSTAGES; s++) {
        CP_WAIT1();
        __syncthreads();              // stage-s data visible; prior compute done
        if (s + 2 < NSTAGES) issue(s + 2);
        CP_COMMIT();

        const uint32_t sA = smbase + (s % RING) * STAGE_B;
        const uint32_t sB = sA + TILE_B;

        #pragma unroll
        for (int w = 0; w < 4; w++) {
            uint32_t af[4][4], bf[2][4];
            #pragma unroll
            for (int mi = 0; mi < 4; mi++)
                ldm_x4(af[mi], sA + swz(a_row + mi * 16, w * 2 + a_chl));
            #pragma unroll
            for (int p = 0; p < 2; p++)
                ldm_x4(bf[p], sB + swz(b_row + p * 16, w * 2 + b_chl));
            #pragma unroll
            for (int mi = 0; mi < 4; mi++) {
                mma16(acc[mi][0], af[mi], &bf[0][0]);
                mma16(acc[mi][1], af[mi], &bf[0][2]);
                mma16(acc[mi][2], af[mi], &bf[1][0]);
                mma16(acc[mi][3], af[mi], &bf[1][2]);
            }
        }
        // no trailing sync: next-iter CP_WAIT1+__syncthreads provides ordering
    }

    #pragma unroll
    for (int mi = 0; mi < 4; mi++) {
        const int row = m0 + wm * 64 + mi * 16 + (lane >> 2);
        #pragma unroll
        for (int ni = 0; ni < 4; ni++) {
            const int col = n0 + wn * 32 + ni * 8 + (lane & 3) * 2;
            *(float2*)(g_logits + (size_t)row * EXPERTS + col)       = make_float2(acc[mi][ni][0], acc[mi][ni][1]);
            *(float2*)(g_logits + (size_t)(row + 8) * EXPERTS + col) = make_float2(acc[mi][ni][2], acc[mi][ni][3]);
        }
    }
}

// ---------------------------------------------------------------------------
// Warp-per-token topk, redux-based rounds; reg-capped for 40 warps/SM.
// ---------------------------------------------------------------------------
__global__ __launch_bounds__(128, 10)
void topk_warp(const float* __restrict__ A, const float* __restrict__ W,
               const float* __restrict__ bias, float* __restrict__ out) {
    const int lane  = threadIdx.x & 31;
    const int wslot = threadIdx.x >> 5;
    const int token = blockIdx.x * 4 + wslot;
    const float* row = g_logits + (size_t)token * EXPERTS;

    __shared__ float s_cb[4][NCAND];
    __shared__ float s_cs[4][NCAND];
    __shared__ int   s_ce[4][NCAND];

    float b[24];
    #pragma unroll
    for (int j = 0; j < 24; j++) b[j] = row[j * 32 + lane];

    float m = b[0];
    #pragma unroll
    for (int j = 1; j < 24; j++) m = fmaxf(m, b[j]);
    #pragma unroll
    for (int off = 16; off; off >>= 1) m = fmaxf(m, __shfl_xor_sync(0xffffffffu, m, off));
    float ssum = 0.0f;
    #pragma unroll
    for (int j = 0; j < 24; j++) { b[j] = expf(b[j] - m); ssum += b[j]; }
    #pragma unroll
    for (int off = 16; off; off >>= 1) ssum += __shfl_xor_sync(0xffffffffu, ssum, off);
    const float inv = 1.0f / ssum;
    #pragma unroll
    for (int j = 0; j < 24; j++) b[j] = fmaf(b[j], inv, __ldg(&bias[j * 32 + lane]));

    for (int sel = 0; sel < NCAND; sel++) {
        float t12[12];
        #pragma unroll
        for (int j = 0; j < 12; j++) t12[j] = fmaxf(b[2 * j], b[2 * j + 1]);
        float t6[6];
        #pragma unroll
        for (int j = 0; j < 6; j++) t6[j] = fmaxf(t12[2 * j], t12[2 * j + 1]);
        float t3a = fmaxf(t6[0], t6[1]), t3b = fmaxf(t6[2], t6[3]), t3c = fmaxf(t6[4], t6[5]);
        const float v = fmaxf(fmaxf(t3a, t3b), t3c);

        const uint32_t gk = __reduce_max_sync(0xffffffffu, fkey(v));
        const float vg = fval(gk);

        uint32_t msk = 0;
        #pragma unroll
        for (int j = 0; j < 24; j++) msk |= (b[j] == vg) ? (1u << j) : 0u;
        const uint32_t cand = msk ? (uint32_t)((__ffs(msk) - 1) * 32 + lane) : 0xFFFFFFFFu;
        const uint32_t idx = __reduce_min_sync(0xffffffffu, cand);

        if ((idx & 31u) == (uint32_t)lane) {
            const int jw = idx >> 5;
            #pragma unroll
            for (int j = 0; j < 24; j++) if (j == jw) b[j] = -CUDART_INF_F;
        }
        if (lane == 0) {
            s_cb[wslot][sel] = vg;
            s_cs[wslot][sel] = vg - __ldg(&bias[idx]);
            s_ce[wslot][sel] = (int)idx;
        }
    }
    __syncwarp();

    unsigned fmask = 0;
    #pragma unroll
    for (int r = 0; r < NCAND - 1; r++)
        if (s_cb[wslot][r] - s_cb[wslot][r + 1] < TAU) fmask |= (3u << r);

    const float* x = A + (size_t)token * HIDDEN;
    while (fmask) {
        const int r = __ffs(fmask) - 1;
        fmask &= fmask - 1;
        const int e = s_ce[wslot][r];
        const float* w = W + (size_t)e * HIDDEN;
        float p = 0.0f;
        #pragma unroll 8
        for (int jj = lane; jj < HIDDEN; jj += 32)
            p = fmaf(x[jj], w[jj], p);
        #pragma unroll
        for (int off = 16; off; off >>= 1)
            p += __shfl_xor_sync(0xffffffffu, p, off);
        if (lane == 0) {
            const float sn = expf(p - m) * inv;
            s_cs[wslot][r] = sn;
            s_cb[wslot][r] = sn + __ldg(&bias[e]);
        }
    }
    __syncwarp();

    if (lane < NCAND) {
        const float mv = s_cb[wslot][lane];
        const int   me = s_ce[wslot][lane];
        int rank = 0;
        #pragma unroll
        for (int j = 0; j < NCAND; j++) {
            const float jv = s_cb[wslot][j];
            const int   je = s_ce[wslot][j];
            if (jv > mv || (jv == mv && je < me)) rank++;
        }
        if (rank < TOPK) {
            out[(size_t)token * TOPK + rank]                         = (float)me;
            out[(size_t)TOKENS * TOPK + (size_t)token * TOPK + rank] = s_cs[wslot][lane] * RSCALE;
        }
    }
}

extern "C" void kernel_launch(void* const* d_in, const int* in_sizes, int n_in,
                              void* d_out, int out_size) {
    const float* A    = (const float*)d_in[0];
    const float* W    = (const float*)d_in[1];
    const float* bias = (const float*)d_in[2];
    float* out = (float*)d_out;

    __half* dAh = nullptr; __half* dWh = nullptr;
    cudaGetSymbolAddress((void**)&dAh, g_Ah);
    cudaGetSymbolAddress((void**)&dWh, g_Wh);

    cvt_all_kernel<<<CVT_BLOCKS, 256>>>((const float4*)A, (const float4*)W,
                                        (uint2*)dAh, (uint2*)dWh);

    cudaFuncSetAttribute(router_gemm_cp, cudaFuncAttributeMaxDynamicSharedMemorySize, GEMM_SMEM);
    dim3 grid(EXPERTS / BN, TOKENS / BM);   // (6, 64)
    router_gemm_cp<<<grid, 256, GEMM_SMEM>>>();

    topk_warp<<<TOKENS / 4, 128>>>(A, W, bias, out);
}